// round 13
// baseline (speedup 1.0000x reference)
#include <cuda_runtime.h>
#include <cuda_bf16.h>
#include <cuda_fp16.h>
#include <math.h>
#include <stdint.h>

#define BATCH 32
#define SEQ   2048
#define DIM   1024
#define MROWS (BATCH * SEQ)   // 65536
#define QP    (BATCH * DIM)   // 32768

// Scratch (no cudaMalloc allowed)
__device__ float  g_qpart[4 * QP];      // 4 K-split partials of q_proj
__device__ float  g_score[2 * MROWS];   // two nt-half partials, no atomics
__device__ __half g_w2h[DIM * DIM];     // W2 pre-converted to fp16 (2 MB)

// ---------------------------------------------------------------------------
// helpers
// ---------------------------------------------------------------------------
__device__ __forceinline__ uint32_t smem_u32(const void* p) {
    return (uint32_t)__cvta_generic_to_shared(p);
}
__device__ __forceinline__ void ldsm4(uint32_t* r, uint32_t a) {
    asm volatile("ldmatrix.sync.aligned.m8n8.x4.shared.b16 {%0,%1,%2,%3}, [%4];"
                 : "=r"(r[0]), "=r"(r[1]), "=r"(r[2]), "=r"(r[3]) : "r"(a));
}
// fp16 m16n8k16, fp32 accumulate
__device__ __forceinline__ void mma_f16(float* c, const uint32_t* a, const uint32_t* b) {
    asm volatile(
        "mma.sync.aligned.m16n8k16.row.col.f32.f16.f16.f32 "
        "{%0,%1,%2,%3}, {%4,%5,%6,%7}, {%8,%9}, {%0,%1,%2,%3};"
        : "+f"(c[0]), "+f"(c[1]), "+f"(c[2]), "+f"(c[3])
        : "r"(a[0]), "r"(a[1]), "r"(a[2]), "r"(a[3]), "r"(b[0]), "r"(b[1]));
}
__device__ __forceinline__ uint32_t packh2(float lo, float hi) {
    __half2 h = __floats2half2_rn(lo, hi);
    return *(uint32_t*)&h;
}
__device__ __forceinline__ float tanh_fast(float x) {
    float y;
    asm("tanh.approx.f32 %0, %1;" : "=f"(y) : "f"(x));
    return y;
}
__device__ __forceinline__ void cpasync16(uint32_t saddr, const void* gaddr) {
    asm volatile("cp.async.cg.shared.global [%0], [%1], 16;"
                 :: "r"(saddr), "l"(gaddr));
}
__device__ __forceinline__ void cpasync_commit() {
    asm volatile("cp.async.commit_group;" ::: "memory");
}
__device__ __forceinline__ void cpasync_wait0() {
    asm volatile("cp.async.wait_group 0;" ::: "memory");
}
// 16B-chunk swizzled offset within an operand tile (row = 4 chunks of 16B).
__device__ __forceinline__ int swz(int row, int c) {
    return row * 64 + (((c ^ ((row + (row >> 2)) & 3)) & 3) << 4);
}

// smem layout for the score kernel
#define OFF_A0  0          // 8 KB
#define OFF_B0  8192       // 16 KB
#define OFF_A1  24576
#define OFF_B1  32768
#define OFF_QSM 49152      // 4 KB
#define OFF_VSM 53248      // 4 KB
#define OFF_SC  57344      // 512 B
#define SMEM_TOTAL 57856

// ---------------------------------------------------------------------------
// Kernel 1: q_proj partials, K-split x4: grid (64 e-tiles, 4 k-splits).
// Each CTA: 16 e-rows x 32 b over K-range [ks*256, ks*256+256).
// Also: each of the 256 CTAs converts 1/256 of W2 to fp16 (g_w2h), and
// CTAs (bx<32, ks==0) zero ctx (d_out poisoned). Stream ordering
// (qproj -> score -> ... -> context) guarantees completion before use.
// ---------------------------------------------------------------------------
__global__ __launch_bounds__(256)
void qproj_kernel(const float* __restrict__ q,
                  const float* __restrict__ W1,
                  const float* __restrict__ W1b,
                  const float* __restrict__ W2,
                  float* __restrict__ qpart,
                  __half* __restrict__ w2h,
                  float* __restrict__ ctx) {
    __shared__ float4 qs4[32 * 32];   // 32 b x 32 chunks (swizzled)
    __shared__ float4 ws4[16 * 32];   // 16 e x 32 chunks

    const int tid = threadIdx.x;
    const int e0  = blockIdx.x * 16;
    const int ks  = blockIdx.y;        // 0..3
    const int b   = tid & 31;
    const int el  = tid >> 5;          // 0..7

    // W2 -> fp16 conversion slice (1024 float4 per CTA)
    {
        const int cid = ks * 64 + blockIdx.x;            // 0..255
        const float4* wsrc = (const float4*)W2 + (size_t)cid * 1024;
        uint2* wdst = (uint2*)w2h + (size_t)cid * 1024;
#pragma unroll
        for (int j = 0; j < 4; ++j) {
            const int idx = tid + j * 256;
            float4 v = wsrc[idx];
            wdst[idx] = make_uint2(packh2(v.x, v.y), packh2(v.z, v.w));
        }
    }

    if (ks == 0 && blockIdx.x < 32) {
#pragma unroll
        for (int i = 0; i < 4; ++i)
            ctx[(size_t)blockIdx.x * DIM + tid + i * 256] = 0.f;
    }

    float acc0 = 0.f, acc1 = 0.f;

#pragma unroll
    for (int kt = 0; kt < 2; ++kt) {
        const int k0 = ks * 256 + kt * 128;
#pragma unroll
        for (int j = 0; j < 4; ++j) {
            int i   = tid + j * 256;
            int row = i >> 5;
            int c4  = i & 31;
            float4 v = *(const float4*)(q + (size_t)row * DIM + k0 + c4 * 4);
            qs4[row * 32 + (c4 ^ row)] = v;
        }
#pragma unroll
        for (int j = 0; j < 2; ++j) {
            int i   = tid + j * 256;
            int row = i >> 5;
            int c4  = i & 31;
            ws4[row * 32 + c4] =
                *(const float4*)(W1 + (size_t)(e0 + row) * DIM + k0 + c4 * 4);
        }
        __syncthreads();
#pragma unroll
        for (int c = 0; c < 32; ++c) {
            float4 qv = qs4[b * 32 + (c ^ b)];
            float4 w0 = ws4[el * 32 + c];
            float4 w1 = ws4[(el + 8) * 32 + c];
            acc0 += qv.x * w0.x + qv.y * w0.y + qv.z * w0.z + qv.w * w0.w;
            acc1 += qv.x * w1.x + qv.y * w1.y + qv.z * w1.z + qv.w * w1.w;
        }
        __syncthreads();
    }
    float* qo = qpart + (size_t)ks * QP;
    const float b0 = (ks == 0) ? W1b[e0 + el]     : 0.f;
    const float b1 = (ks == 0) ? W1b[e0 + el + 8] : 0.f;
    qo[b * DIM + e0 + el]     = acc0 + b0;
    qo[b * DIM + e0 + el + 8] = acc1 + b1;
}

// ---------------------------------------------------------------------------
// Kernel 2 (dominant): fp16 mma.sync fused score GEMM, nt-split over
// blockIdx.y; each half writes its own partial buffer (no atomics).
// B (W2, fp16) streamed gmem->smem via cp.async; B fragments via ldsm x4.
//   score_part[y][m] = sum_{n in half} Vw[n]*tanh(D[m,n] + qproj[b,n] + W2b[n])
// qproj reconstructed from the 4 K-split partials at qsm load time.
// (V_b dropped: softmax is shift-invariant and score is not an output.)
// ---------------------------------------------------------------------------
__global__ __launch_bounds__(256, 1)
void score_f16_kernel(const float* __restrict__ key,
                      const __half* __restrict__ w2h,
                      const float* __restrict__ W2b,
                      const float* __restrict__ qpart,
                      const float* __restrict__ Vw,
                      float* __restrict__ score_g) {
    extern __shared__ char smem[];
    const uint32_t sb = smem_u32(smem);
    float* qsm = (float*)(smem + OFF_QSM);
    float* vsm = (float*)(smem + OFF_VSM);
    float* score_sm = (float*)(smem + OFF_SC);

    const int tid  = threadIdx.x;
    const int lane = tid & 31;
    const int wid  = tid >> 5;
    const int warp_m = wid >> 2;        // 0..1
    const int warp_n = wid & 3;         // 0..3
    const int row0 = blockIdx.x * 128;
    const int b    = row0 >> 11;
    const int nt0  = blockIdx.y * 2;    // this CTA's nt range: nt0, nt0+1

    for (int i = tid; i < DIM; i += 256) {
        const int o = b * DIM + i;
        qsm[i] = qpart[o] + qpart[QP + o] + qpart[2 * QP + o] + qpart[3 * QP + o]
               + W2b[i];
        vsm[i] = Vw[i];
    }
    if (tid < 128) score_sm[tid] = 0.f;
    __syncthreads();

    // ldmatrix lane constants
    const int r8      = lane & 7;
    const int mlocal  = (((lane >> 3) & 1) << 3) + r8;  // A x4 row-in-frag
    const int a_chalf = lane >> 4;                      // A: k8-half select
    const int mrow_t  = warp_m * 64 + mlocal;           // + mf*16
    // B x4 lane mapping: group g = lane>>3; matrix pair member = lane>>4,
    // k8-half = g&1.  m0..m3 = (nf_even,k0),(nf_even,k1),(nf_odd,k0),(nf_odd,k1)
    const int b_kh    = (lane >> 3) & 1;
    const int nrow4_t = warp_n * 64 + ((lane >> 4) << 3) + r8;  // + nfp*16

    // global-load lane mapping: thread -> (row, 16B chunk)
    const int gm = tid >> 2;            // 0..63 (+64 per iter)
    const int gc = tid & 3;             // chunk 0..3

    const float* keyA = key + (size_t)row0 * DIM;

    float sp[8];
#pragma unroll
    for (int j = 0; j < 8; ++j) sp[j] = 0.f;

    const uint32_t offA[2] = {OFF_A0, OFF_A1};
    const uint32_t offB[2] = {OFF_B0, OFF_B1};

    for (int p = 0; p < 2; ++p) {
        const int nt = nt0 + p;
        const __half* w2p = w2h + (size_t)(nt * 256) * DIM;

        float acc[4][8][4];
#pragma unroll
        for (int mf = 0; mf < 4; ++mf)
#pragma unroll
            for (int nf = 0; nf < 8; ++nf)
#pragma unroll
                for (int q = 0; q < 4; ++q) acc[mf][nf][q] = 0.f;

        float4 ra[2][2];
        // prologue: k-chunk 0 -> buf 0 (A via regs+cvt, B via cp.async)
#pragma unroll
        for (int i = 0; i < 4; ++i)
            cpasync16(sb + OFF_B0 + swz(gm + i * 64, gc),
                      w2p + (size_t)(gm + i * 64) * DIM + gc * 8);
        cpasync_commit();
#pragma unroll
        for (int i = 0; i < 2; ++i) {
            const float* pp = keyA + (size_t)(gm + i * 64) * DIM + gc * 8;
            ra[i][0] = *(const float4*)pp;
            ra[i][1] = *(const float4*)(pp + 4);
        }
#pragma unroll
        for (int i = 0; i < 2; ++i) {
            uint4 v = { packh2(ra[i][0].x, ra[i][0].y), packh2(ra[i][0].z, ra[i][0].w),
                        packh2(ra[i][1].x, ra[i][1].y), packh2(ra[i][1].z, ra[i][1].w) };
            *(uint4*)(smem + OFF_A0 + swz(gm + i * 64, gc)) = v;
        }
        cpasync_wait0();
        __syncthreads();

        for (int kc = 0; kc < 32; ++kc) {          // 32 chunks of K=32 fp16
            const int buf = kc & 1;
            const bool more = kc < 31;
            if (more) {
                const int k0 = (kc + 1) * 32;
                const int nbuf = buf ^ 1;
                // B -> nbuf via cp.async, issued before compute for overlap.
                // Safe: __syncthreads() at end of kc-1 drained nbuf readers.
#pragma unroll
                for (int i = 0; i < 4; ++i)
                    cpasync16(sb + offB[nbuf] + swz(gm + i * 64, gc),
                              w2p + (size_t)(gm + i * 64) * DIM + k0 + gc * 8);
                cpasync_commit();
#pragma unroll
                for (int i = 0; i < 2; ++i) {
                    const float* pp = keyA + (size_t)(gm + i * 64) * DIM + k0 + gc * 8;
                    ra[i][0] = *(const float4*)pp;
                    ra[i][1] = *(const float4*)(pp + 4);
                }
            }

            const uint32_t ab = sb + offA[buf];
            const uint32_t bb = sb + offB[buf];
#pragma unroll
            for (int s = 0; s < 2; ++s) {          // two k16 MMA steps
                uint32_t afr[4][4];
                uint32_t bfr[8][2];
#pragma unroll
                for (int mf = 0; mf < 4; ++mf)
                    ldsm4(afr[mf], ab + swz(mrow_t + mf * 16, 2 * s + a_chalf));
#pragma unroll
                for (int nfp = 0; nfp < 4; ++nfp) {
                    uint32_t r[4];
                    ldsm4(r, bb + swz(nrow4_t + nfp * 16, 2 * s + b_kh));
                    bfr[2 * nfp][0]     = r[0];
                    bfr[2 * nfp][1]     = r[1];
                    bfr[2 * nfp + 1][0] = r[2];
                    bfr[2 * nfp + 1][1] = r[3];
                }
#pragma unroll
                for (int mf = 0; mf < 4; ++mf)
#pragma unroll
                    for (int nf = 0; nf < 8; ++nf)
                        mma_f16(acc[mf][nf], afr[mf], bfr[nf]);
            }

            if (more) {
                const int nbuf = buf ^ 1;
#pragma unroll
                for (int i = 0; i < 2; ++i) {
                    uint4 v = { packh2(ra[i][0].x, ra[i][0].y), packh2(ra[i][0].z, ra[i][0].w),
                                packh2(ra[i][1].x, ra[i][1].y), packh2(ra[i][1].z, ra[i][1].w) };
                    *(uint4*)(smem + offA[nbuf] + swz(gm + i * 64, gc)) = v;
                }
                cpasync_wait0();
                __syncthreads();
            }
        }

        // fused epilogue: tanh + V-dot into per-thread row partials
        const int ncol0 = nt * 256 + warp_n * 64 + (lane & 3) * 2;
#pragma unroll
        for (int mf = 0; mf < 4; ++mf) {
#pragma unroll
            for (int nf = 0; nf < 8; ++nf) {
                const int n0 = ncol0 + nf * 8;
                const float q0 = qsm[n0],     v0 = vsm[n0];
                const float q1 = qsm[n0 + 1], v1 = vsm[n0 + 1];
                float* c4 = acc[mf][nf];
                sp[mf * 2 + 0] += tanh_fast(c4[0] + q0) * v0 + tanh_fast(c4[1] + q1) * v1;
                sp[mf * 2 + 1] += tanh_fast(c4[2] + q0) * v0 + tanh_fast(c4[3] + q1) * v1;
            }
        }
        // next pass's prologue targets buf0; gated by its own wait+sync
    }

    // reduce quad (lanes sharing the same row) and accumulate to smem
#pragma unroll
    for (int j = 0; j < 8; ++j) {
        float v = sp[j];
        v += __shfl_xor_sync(0xffffffffu, v, 1);
        v += __shfl_xor_sync(0xffffffffu, v, 2);
        if ((lane & 3) == 0) {
            const int row = warp_m * 64 + (j >> 1) * 16 + (j & 1) * 8 + (lane >> 2);
            atomicAdd(&score_sm[row], v);
        }
    }
    __syncthreads();
    if (tid < 128)
        score_g[blockIdx.y * MROWS + row0 + tid] = score_sm[tid];   // plain store
}

// ---------------------------------------------------------------------------
// Kernel 3: softmax over S per batch row (sums the two partial buffers),
// writes attn.
// ---------------------------------------------------------------------------
__global__ void softmax_kernel(const float* __restrict__ score,
                               float* __restrict__ attn) {
    const int b   = blockIdx.x;
    const int tid = threadIdx.x;   // 256
    __shared__ float red[256];
    const float* sr0 = score + (size_t)b * SEQ;
    const float* sr1 = score + MROWS + (size_t)b * SEQ;

    float v[8];
    float mx = -INFINITY;
#pragma unroll
    for (int i = 0; i < 8; ++i) {
        const int idx = tid + i * 256;
        v[i] = sr0[idx] + sr1[idx];
        mx = fmaxf(mx, v[i]);
    }
    red[tid] = mx;
    __syncthreads();
    for (int s = 128; s; s >>= 1) {
        if (tid < s) red[tid] = fmaxf(red[tid], red[tid + s]);
        __syncthreads();
    }
    const float m = red[0];
    __syncthreads();

    float sum = 0.f;
#pragma unroll
    for (int i = 0; i < 8; ++i) {
        v[i] = expf(v[i] - m);
        sum += v[i];
    }
    red[tid] = sum;
    __syncthreads();
    for (int s = 128; s; s >>= 1) {
        if (tid < s) red[tid] += red[tid + s];
        __syncthreads();
    }
    const float inv = 1.f / red[0];
#pragma unroll
    for (int i = 0; i < 8; ++i)
        attn[(size_t)b * SEQ + tid + i * 256] = v[i] * inv;
}

// ---------------------------------------------------------------------------
// Kernel 4: context[b,d] += sum_{s in chunk} attn[b,s] * value[b,s,d]
// grid (B, 32 s-chunks) x 256 thr; each thread owns one float4 of d.
// ---------------------------------------------------------------------------
__global__ __launch_bounds__(256)
void context_kernel(const float* __restrict__ attn,
                    const float* __restrict__ value,
                    float* __restrict__ ctx) {
    const int b   = blockIdx.x;
    const int s0  = blockIdx.y * 64;
    const int tid = threadIdx.x;
    __shared__ float a_sh[64];

    if (tid < 64) a_sh[tid] = attn[(size_t)b * SEQ + s0 + tid];
    __syncthreads();

    const float4* vp = (const float4*)(value + ((size_t)b * SEQ + s0) * DIM) + tid;
    float ax = 0.f, ay = 0.f, az = 0.f, aw = 0.f;
#pragma unroll 8
    for (int s = 0; s < 64; ++s) {
        const float a = a_sh[s];
        const float4 w = vp[(size_t)s * 256];
        ax = fmaf(a, w.x, ax);
        ay = fmaf(a, w.y, ay);
        az = fmaf(a, w.z, az);
        aw = fmaf(a, w.w, aw);
    }
    float* cp = ctx + (size_t)b * DIM + tid * 4;
    atomicAdd(cp + 0, ax);
    atomicAdd(cp + 1, ay);
    atomicAdd(cp + 2, az);
    atomicAdd(cp + 3, aw);
}

// ---------------------------------------------------------------------------
extern "C" void kernel_launch(void* const* d_in, const int* in_sizes, int n_in,
                              void* d_out, int out_size) {
    const float* query = (const float*)d_in[0];
    const float* key   = (const float*)d_in[1];
    const float* value = (const float*)d_in[2];
    const float* W1w   = (const float*)d_in[3];
    const float* W1b   = (const float*)d_in[4];
    const float* W2w   = (const float*)d_in[5];
    const float* W2b   = (const float*)d_in[6];
    const float* Vw    = (const float*)d_in[7];
    // d_in[8] = V_b: dropped — softmax is shift-invariant, score not an output

    float* out  = (float*)d_out;
    float* ctx  = out;                        // [B, DIM]
    float* attn = out + (size_t)BATCH * DIM;  // [B, S]

    float*  qpart;  cudaGetSymbolAddress((void**)&qpart, g_qpart);
    float*  score;  cudaGetSymbolAddress((void**)&score, g_score);
    __half* w2h;    cudaGetSymbolAddress((void**)&w2h, g_w2h);

    // 1) q_proj K-split x4 partials; also converts W2->fp16 and zeroes ctx
    qproj_kernel<<<dim3(64, 4), 256>>>(query, W1w, W1b, W2w, qpart, w2h, ctx);

    // 2) fp16 mma.sync fused score GEMM, nt-split x2, partial buffers
    cudaFuncSetAttribute(score_f16_kernel,
                         cudaFuncAttributeMaxDynamicSharedMemorySize, SMEM_TOTAL);
    score_f16_kernel<<<dim3(MROWS / 128, 2), 256, SMEM_TOTAL>>>(key, w2h, W2b,
                                                                qpart, Vw, score);

    // 3) softmax (sums partials) -> attn
    softmax_kernel<<<BATCH, 256>>>(score, attn);

    // 4) context = attn^T @ value (s-split x32, float4 streams)
    context_kernel<<<dim3(BATCH, 32), 256>>>(attn, value, ctx);
}

// round 14
// speedup vs baseline: 1.0378x; 1.0378x over previous
#include <cuda_runtime.h>
#include <cuda_bf16.h>
#include <cuda_fp16.h>
#include <math.h>
#include <stdint.h>

#define BATCH 32
#define SEQ   2048
#define DIM   1024
#define MROWS (BATCH * SEQ)   // 65536
#define QP    (BATCH * DIM)   // 32768

// Scratch (no cudaMalloc allowed)
__device__ float  g_qpart[4 * QP];      // 4 K-split partials of q_proj
__device__ float  g_score[2 * MROWS];   // two nt-half partials, no atomics
__device__ __half g_w2h[DIM * DIM];     // W2 pre-converted to fp16 (2 MB)

// ---------------------------------------------------------------------------
// helpers
// ---------------------------------------------------------------------------
__device__ __forceinline__ uint32_t smem_u32(const void* p) {
    return (uint32_t)__cvta_generic_to_shared(p);
}
__device__ __forceinline__ void ldsm4(uint32_t* r, uint32_t a) {
    asm volatile("ldmatrix.sync.aligned.m8n8.x4.shared.b16 {%0,%1,%2,%3}, [%4];"
                 : "=r"(r[0]), "=r"(r[1]), "=r"(r[2]), "=r"(r[3]) : "r"(a));
}
__device__ __forceinline__ void ldsm2(uint32_t* r, uint32_t a) {
    asm volatile("ldmatrix.sync.aligned.m8n8.x2.shared.b16 {%0,%1}, [%2];"
                 : "=r"(r[0]), "=r"(r[1]) : "r"(a));
}
// fp16 m16n8k16, fp32 accumulate
__device__ __forceinline__ void mma_f16(float* c, const uint32_t* a, const uint32_t* b) {
    asm volatile(
        "mma.sync.aligned.m16n8k16.row.col.f32.f16.f16.f32 "
        "{%0,%1,%2,%3}, {%4,%5,%6,%7}, {%8,%9}, {%0,%1,%2,%3};"
        : "+f"(c[0]), "+f"(c[1]), "+f"(c[2]), "+f"(c[3])
        : "r"(a[0]), "r"(a[1]), "r"(a[2]), "r"(a[3]), "r"(b[0]), "r"(b[1]));
}
__device__ __forceinline__ uint32_t packh2(float lo, float hi) {
    __half2 h = __floats2half2_rn(lo, hi);
    return *(uint32_t*)&h;
}
__device__ __forceinline__ float tanh_fast(float x) {
    float y;
    asm("tanh.approx.f32 %0, %1;" : "=f"(y) : "f"(x));
    return y;
}
// 16B-chunk swizzled offset within an operand tile (row = 4 chunks of 16B).
__device__ __forceinline__ int swz(int row, int c) {
    return row * 64 + (((c ^ ((row + (row >> 2)) & 3)) & 3) << 4);
}

// smem layout for the score kernel
#define OFF_A0  0          // 8 KB
#define OFF_B0  8192       // 16 KB
#define OFF_A1  24576
#define OFF_B1  32768
#define OFF_QSM 49152      // 4 KB
#define OFF_VSM 53248      // 4 KB
#define OFF_SC  57344      // 512 B
#define SMEM_TOTAL 57856

// ---------------------------------------------------------------------------
// Kernel 1: q_proj partials, K-split x4: grid (64 e-tiles, 4 k-splits).
// Each CTA: 16 e-rows x 32 b over K-range [ks*256, ks*256+256).
// Also: each of the 256 CTAs converts 1/256 of W2 to fp16 (g_w2h), and
// CTAs (bx<32, ks==0) zero ctx (d_out poisoned). Stream ordering
// (qproj -> score -> ... -> context) guarantees completion before use.
// ---------------------------------------------------------------------------
__global__ __launch_bounds__(256)
void qproj_kernel(const float* __restrict__ q,
                  const float* __restrict__ W1,
                  const float* __restrict__ W1b,
                  const float* __restrict__ W2,
                  float* __restrict__ qpart,
                  __half* __restrict__ w2h,
                  float* __restrict__ ctx) {
    __shared__ float4 qs4[32 * 32];   // 32 b x 32 chunks (swizzled)
    __shared__ float4 ws4[16 * 32];   // 16 e x 32 chunks

    const int tid = threadIdx.x;
    const int e0  = blockIdx.x * 16;
    const int ks  = blockIdx.y;        // 0..3
    const int b   = tid & 31;
    const int el  = tid >> 5;          // 0..7

    // W2 -> fp16 conversion slice (1024 float4 per CTA)
    {
        const int cid = ks * 64 + blockIdx.x;            // 0..255
        const float4* wsrc = (const float4*)W2 + (size_t)cid * 1024;
        uint2* wdst = (uint2*)w2h + (size_t)cid * 1024;
#pragma unroll
        for (int j = 0; j < 4; ++j) {
            const int idx = tid + j * 256;
            float4 v = wsrc[idx];
            wdst[idx] = make_uint2(packh2(v.x, v.y), packh2(v.z, v.w));
        }
    }

    if (ks == 0 && blockIdx.x < 32) {
#pragma unroll
        for (int i = 0; i < 4; ++i)
            ctx[(size_t)blockIdx.x * DIM + tid + i * 256] = 0.f;
    }

    float acc0 = 0.f, acc1 = 0.f;

#pragma unroll
    for (int kt = 0; kt < 2; ++kt) {
        const int k0 = ks * 256 + kt * 128;
#pragma unroll
        for (int j = 0; j < 4; ++j) {
            int i   = tid + j * 256;
            int row = i >> 5;
            int c4  = i & 31;
            float4 v = *(const float4*)(q + (size_t)row * DIM + k0 + c4 * 4);
            qs4[row * 32 + (c4 ^ row)] = v;
        }
#pragma unroll
        for (int j = 0; j < 2; ++j) {
            int i   = tid + j * 256;
            int row = i >> 5;
            int c4  = i & 31;
            ws4[row * 32 + c4] =
                *(const float4*)(W1 + (size_t)(e0 + row) * DIM + k0 + c4 * 4);
        }
        __syncthreads();
#pragma unroll
        for (int c = 0; c < 32; ++c) {
            float4 qv = qs4[b * 32 + (c ^ b)];
            float4 w0 = ws4[el * 32 + c];
            float4 w1 = ws4[(el + 8) * 32 + c];
            acc0 += qv.x * w0.x + qv.y * w0.y + qv.z * w0.z + qv.w * w0.w;
            acc1 += qv.x * w1.x + qv.y * w1.y + qv.z * w1.z + qv.w * w1.w;
        }
        __syncthreads();
    }
    float* qo = qpart + (size_t)ks * QP;
    const float b0 = (ks == 0) ? W1b[e0 + el]     : 0.f;
    const float b1 = (ks == 0) ? W1b[e0 + el + 8] : 0.f;
    qo[b * DIM + e0 + el]     = acc0 + b0;
    qo[b * DIM + e0 + el + 8] = acc1 + b1;
}

// ---------------------------------------------------------------------------
// Kernel 2 (dominant): fp16 mma.sync fused score GEMM, nt-split over
// blockIdx.y; each half writes its own partial buffer (no atomics).
// B (W2) is pre-converted fp16 — loaded straight to smem, no cvt.
//   score_part[y][m] = sum_{n in half} Vw[n]*tanh(D[m,n] + qproj[b,n] + W2b[n])
// qproj reconstructed from the 4 K-split partials at qsm load time.
// (V_b dropped: softmax is shift-invariant and score is not an output.)
// ---------------------------------------------------------------------------
__global__ __launch_bounds__(256, 1)
void score_f16_kernel(const float* __restrict__ key,
                      const __half* __restrict__ w2h,
                      const float* __restrict__ W2b,
                      const float* __restrict__ qpart,
                      const float* __restrict__ Vw,
                      float* __restrict__ score_g) {
    extern __shared__ char smem[];
    const uint32_t sb = smem_u32(smem);
    float* qsm = (float*)(smem + OFF_QSM);
    float* vsm = (float*)(smem + OFF_VSM);
    float* score_sm = (float*)(smem + OFF_SC);

    const int tid  = threadIdx.x;
    const int lane = tid & 31;
    const int wid  = tid >> 5;
    const int warp_m = wid >> 2;        // 0..1
    const int warp_n = wid & 3;         // 0..3
    const int row0 = blockIdx.x * 128;
    const int b    = row0 >> 11;
    const int nt0  = blockIdx.y * 2;    // this CTA's nt range: nt0, nt0+1

    for (int i = tid; i < DIM; i += 256) {
        const int o = b * DIM + i;
        qsm[i] = qpart[o] + qpart[QP + o] + qpart[2 * QP + o] + qpart[3 * QP + o]
               + W2b[i];
        vsm[i] = Vw[i];
    }
    if (tid < 128) score_sm[tid] = 0.f;
    __syncthreads();

    // ldmatrix lane constants (chunk = 8 fp16 = one k8 half of a k16 step)
    const int r8      = lane & 7;
    const int mlocal  = (((lane >> 3) & 1) << 3) + r8;  // A x4 row-in-frag
    const int a_chalf = lane >> 4;                      // A: k8-half select
    const int b_chalf = (lane >> 3) & 1;                // B: k8-half select
    const int mrow_t  = warp_m * 64 + mlocal;           // + mf*16
    const int nrow_t  = warp_n * 64 + r8;               // + nf*8

    // global-load lane mapping: thread -> (row, 16B-fp16 chunk)
    const int gm = tid >> 2;            // 0..63 (+64 per iter)
    const int gc = tid & 3;             // chunk 0..3

    const float* keyA = key + (size_t)row0 * DIM;

    float sp[8];
#pragma unroll
    for (int j = 0; j < 8; ++j) sp[j] = 0.f;

    const uint32_t offA[2] = {OFF_A0, OFF_A1};
    const uint32_t offB[2] = {OFF_B0, OFF_B1};

    for (int p = 0; p < 2; ++p) {
        const int nt = nt0 + p;
        const __half* w2p = w2h + (size_t)(nt * 256) * DIM;

        float acc[4][8][4];
#pragma unroll
        for (int mf = 0; mf < 4; ++mf)
#pragma unroll
            for (int nf = 0; nf < 8; ++nf)
#pragma unroll
                for (int q = 0; q < 4; ++q) acc[mf][nf][q] = 0.f;

        float4 ra[2][2];
        uint4  rbh[4];
        // prologue: k-chunk 0 -> buf 0
#pragma unroll
        for (int i = 0; i < 2; ++i) {
            const float* pp = keyA + (size_t)(gm + i * 64) * DIM + gc * 8;
            ra[i][0] = *(const float4*)pp;
            ra[i][1] = *(const float4*)(pp + 4);
        }
#pragma unroll
        for (int i = 0; i < 4; ++i)
            rbh[i] = *(const uint4*)(w2p + (size_t)(gm + i * 64) * DIM + gc * 8);
#pragma unroll
        for (int i = 0; i < 2; ++i) {
            uint4 v = { packh2(ra[i][0].x, ra[i][0].y), packh2(ra[i][0].z, ra[i][0].w),
                        packh2(ra[i][1].x, ra[i][1].y), packh2(ra[i][1].z, ra[i][1].w) };
            *(uint4*)(smem + OFF_A0 + swz(gm + i * 64, gc)) = v;
        }
#pragma unroll
        for (int i = 0; i < 4; ++i)
            *(uint4*)(smem + OFF_B0 + swz(gm + i * 64, gc)) = rbh[i];
        __syncthreads();

        for (int kc = 0; kc < 32; ++kc) {          // 32 chunks of K=32 fp16
            const int buf = kc & 1;
            const bool more = kc < 31;
            if (more) {
                const int k0 = (kc + 1) * 32;
#pragma unroll
                for (int i = 0; i < 2; ++i) {
                    const float* pp = keyA + (size_t)(gm + i * 64) * DIM + k0 + gc * 8;
                    ra[i][0] = *(const float4*)pp;
                    ra[i][1] = *(const float4*)(pp + 4);
                }
#pragma unroll
                for (int i = 0; i < 4; ++i)
                    rbh[i] = *(const uint4*)(w2p + (size_t)(gm + i * 64) * DIM + k0 + gc * 8);
            }

            const uint32_t ab = sb + offA[buf];
            const uint32_t bb = sb + offB[buf];
#pragma unroll
            for (int s = 0; s < 2; ++s) {          // two k16 MMA steps
                uint32_t afr[4][4];
                uint32_t bfr[8][2];
#pragma unroll
                for (int mf = 0; mf < 4; ++mf)
                    ldsm4(afr[mf], ab + swz(mrow_t + mf * 16, 2 * s + a_chalf));
#pragma unroll
                for (int nf = 0; nf < 8; ++nf)
                    ldsm2(bfr[nf], bb + swz(nrow_t + nf * 8, 2 * s + b_chalf));
#pragma unroll
                for (int mf = 0; mf < 4; ++mf)
#pragma unroll
                    for (int nf = 0; nf < 8; ++nf)
                        mma_f16(acc[mf][nf], afr[mf], bfr[nf]);
            }

            if (more) {
                const int nbuf = buf ^ 1;
#pragma unroll
                for (int i = 0; i < 2; ++i) {
                    uint4 v = { packh2(ra[i][0].x, ra[i][0].y), packh2(ra[i][0].z, ra[i][0].w),
                                packh2(ra[i][1].x, ra[i][1].y), packh2(ra[i][1].z, ra[i][1].w) };
                    *(uint4*)(smem + offA[nbuf] + swz(gm + i * 64, gc)) = v;
                }
#pragma unroll
                for (int i = 0; i < 4; ++i)
                    *(uint4*)(smem + offB[nbuf] + swz(gm + i * 64, gc)) = rbh[i];
                __syncthreads();
            }
        }

        // fused epilogue: tanh + V-dot into per-thread row partials
        const int ncol0 = nt * 256 + warp_n * 64 + (lane & 3) * 2;
#pragma unroll
        for (int mf = 0; mf < 4; ++mf) {
#pragma unroll
            for (int nf = 0; nf < 8; ++nf) {
                const int n0 = ncol0 + nf * 8;
                const float q0 = qsm[n0],     v0 = vsm[n0];
                const float q1 = qsm[n0 + 1], v1 = vsm[n0 + 1];
                float* c4 = acc[mf][nf];
                sp[mf * 2 + 0] += tanh_fast(c4[0] + q0) * v0 + tanh_fast(c4[1] + q1) * v1;
                sp[mf * 2 + 1] += tanh_fast(c4[2] + q0) * v0 + tanh_fast(c4[3] + q1) * v1;
            }
        }
        // next pass's prologue STS targets buf0; gated by its own __syncthreads()
    }

    // reduce quad (lanes sharing the same row) and accumulate to smem
#pragma unroll
    for (int j = 0; j < 8; ++j) {
        float v = sp[j];
        v += __shfl_xor_sync(0xffffffffu, v, 1);
        v += __shfl_xor_sync(0xffffffffu, v, 2);
        if ((lane & 3) == 0) {
            const int row = warp_m * 64 + (j >> 1) * 16 + (j & 1) * 8 + (lane >> 2);
            atomicAdd(&score_sm[row], v);
        }
    }
    __syncthreads();
    if (tid < 128)
        score_g[blockIdx.y * MROWS + row0 + tid] = score_sm[tid];   // plain store
}

// ---------------------------------------------------------------------------
// Kernel 3: softmax over S per batch row (sums the two partial buffers),
// writes attn.
// ---------------------------------------------------------------------------
__global__ void softmax_kernel(const float* __restrict__ score,
                               float* __restrict__ attn) {
    const int b   = blockIdx.x;
    const int tid = threadIdx.x;   // 256
    __shared__ float red[256];
    const float* sr0 = score + (size_t)b * SEQ;
    const float* sr1 = score + MROWS + (size_t)b * SEQ;

    float v[8];
    float mx = -INFINITY;
#pragma unroll
    for (int i = 0; i < 8; ++i) {
        const int idx = tid + i * 256;
        v[i] = sr0[idx] + sr1[idx];
        mx = fmaxf(mx, v[i]);
    }
    red[tid] = mx;
    __syncthreads();
    for (int s = 128; s; s >>= 1) {
        if (tid < s) red[tid] = fmaxf(red[tid], red[tid + s]);
        __syncthreads();
    }
    const float m = red[0];
    __syncthreads();

    float sum = 0.f;
#pragma unroll
    for (int i = 0; i < 8; ++i) {
        v[i] = expf(v[i] - m);
        sum += v[i];
    }
    red[tid] = sum;
    __syncthreads();
    for (int s = 128; s; s >>= 1) {
        if (tid < s) red[tid] += red[tid + s];
        __syncthreads();
    }
    const float inv = 1.f / red[0];
#pragma unroll
    for (int i = 0; i < 8; ++i)
        attn[(size_t)b * SEQ + tid + i * 256] = v[i] * inv;
}

// ---------------------------------------------------------------------------
// Kernel 4: context[b,d] += sum_{s in chunk} attn[b,s] * value[b,s,d]
// grid (B, 32 s-chunks) x 256 thr; each thread owns one float4 of d.
// ---------------------------------------------------------------------------
__global__ __launch_bounds__(256)
void context_kernel(const float* __restrict__ attn,
                    const float* __restrict__ value,
                    float* __restrict__ ctx) {
    const int b   = blockIdx.x;
    const int s0  = blockIdx.y * 64;
    const int tid = threadIdx.x;
    __shared__ float a_sh[64];

    if (tid < 64) a_sh[tid] = attn[(size_t)b * SEQ + s0 + tid];
    __syncthreads();

    const float4* vp = (const float4*)(value + ((size_t)b * SEQ + s0) * DIM) + tid;
    float ax = 0.f, ay = 0.f, az = 0.f, aw = 0.f;
#pragma unroll 8
    for (int s = 0; s < 64; ++s) {
        const float a = a_sh[s];
        const float4 w = vp[(size_t)s * 256];
        ax = fmaf(a, w.x, ax);
        ay = fmaf(a, w.y, ay);
        az = fmaf(a, w.z, az);
        aw = fmaf(a, w.w, aw);
    }
    float* cp = ctx + (size_t)b * DIM + tid * 4;
    atomicAdd(cp + 0, ax);
    atomicAdd(cp + 1, ay);
    atomicAdd(cp + 2, az);
    atomicAdd(cp + 3, aw);
}

// ---------------------------------------------------------------------------
extern "C" void kernel_launch(void* const* d_in, const int* in_sizes, int n_in,
                              void* d_out, int out_size) {
    const float* query = (const float*)d_in[0];
    const float* key   = (const float*)d_in[1];
    const float* value = (const float*)d_in[2];
    const float* W1w   = (const float*)d_in[3];
    const float* W1b   = (const float*)d_in[4];
    const float* W2w   = (const float*)d_in[5];
    const float* W2b   = (const float*)d_in[6];
    const float* Vw    = (const float*)d_in[7];
    // d_in[8] = V_b: dropped — softmax is shift-invariant, score not an output

    float* out  = (float*)d_out;
    float* ctx  = out;                        // [B, DIM]
    float* attn = out + (size_t)BATCH * DIM;  // [B, S]

    float*  qpart;  cudaGetSymbolAddress((void**)&qpart, g_qpart);
    float*  score;  cudaGetSymbolAddress((void**)&score, g_score);
    __half* w2h;    cudaGetSymbolAddress((void**)&w2h, g_w2h);

    // 1) q_proj K-split x4 partials; also converts W2->fp16 and zeroes ctx
    qproj_kernel<<<dim3(64, 4), 256>>>(query, W1w, W1b, W2w, qpart, w2h, ctx);

    // 2) fp16 mma.sync fused score GEMM, nt-split x2, partial buffers
    cudaFuncSetAttribute(score_f16_kernel,
                         cudaFuncAttributeMaxDynamicSharedMemorySize, SMEM_TOTAL);
    score_f16_kernel<<<dim3(MROWS / 128, 2), 256, SMEM_TOTAL>>>(key, w2h, W2b,
                                                                qpart, Vw, score);

    // 3) softmax (sums partials) -> attn
    softmax_kernel<<<BATCH, 256>>>(score, attn);

    // 4) context = attn^T @ value (s-split x32, float4 streams)
    context_kernel<<<dim3(BATCH, 32), 256>>>(attn, value, ctx);
}

// round 15
// speedup vs baseline: 1.0635x; 1.0248x over previous
#include <cuda_runtime.h>
#include <cuda_bf16.h>
#include <cuda_fp16.h>
#include <math.h>
#include <stdint.h>

#define BATCH 32
#define SEQ   2048
#define DIM   1024
#define MROWS (BATCH * SEQ)   // 65536
#define QP    (BATCH * DIM)   // 32768

// batch split for stream overlap: G1 = batches [0,28), G2 = [28,32)
#define B_G1  28

// Scratch (no cudaMalloc allowed)
__device__ float  g_qpart[4 * QP];      // 4 K-split partials of q_proj
__device__ float  g_score[2 * MROWS];   // two nt-half partials, no atomics
__device__ __half g_w2h[DIM * DIM];     // W2 pre-converted to fp16 (2 MB)

// ---------------------------------------------------------------------------
// helpers
// ---------------------------------------------------------------------------
__device__ __forceinline__ uint32_t smem_u32(const void* p) {
    return (uint32_t)__cvta_generic_to_shared(p);
}
__device__ __forceinline__ void ldsm4(uint32_t* r, uint32_t a) {
    asm volatile("ldmatrix.sync.aligned.m8n8.x4.shared.b16 {%0,%1,%2,%3}, [%4];"
                 : "=r"(r[0]), "=r"(r[1]), "=r"(r[2]), "=r"(r[3]) : "r"(a));
}
__device__ __forceinline__ void ldsm2(uint32_t* r, uint32_t a) {
    asm volatile("ldmatrix.sync.aligned.m8n8.x2.shared.b16 {%0,%1}, [%2];"
                 : "=r"(r[0]), "=r"(r[1]) : "r"(a));
}
// fp16 m16n8k16, fp32 accumulate
__device__ __forceinline__ void mma_f16(float* c, const uint32_t* a, const uint32_t* b) {
    asm volatile(
        "mma.sync.aligned.m16n8k16.row.col.f32.f16.f16.f32 "
        "{%0,%1,%2,%3}, {%4,%5,%6,%7}, {%8,%9}, {%0,%1,%2,%3};"
        : "+f"(c[0]), "+f"(c[1]), "+f"(c[2]), "+f"(c[3])
        : "r"(a[0]), "r"(a[1]), "r"(a[2]), "r"(a[3]), "r"(b[0]), "r"(b[1]));
}
__device__ __forceinline__ uint32_t packh2(float lo, float hi) {
    __half2 h = __floats2half2_rn(lo, hi);
    return *(uint32_t*)&h;
}
__device__ __forceinline__ float tanh_fast(float x) {
    float y;
    asm("tanh.approx.f32 %0, %1;" : "=f"(y) : "f"(x));
    return y;
}
// 16B-chunk swizzled offset within an operand tile (row = 4 chunks of 16B).
__device__ __forceinline__ int swz(int row, int c) {
    return row * 64 + (((c ^ ((row + (row >> 2)) & 3)) & 3) << 4);
}

// smem layout for the score kernel
#define OFF_A0  0          // 8 KB
#define OFF_B0  8192       // 16 KB
#define OFF_A1  24576
#define OFF_B1  32768
#define OFF_QSM 49152      // 4 KB
#define OFF_VSM 53248      // 4 KB
#define OFF_SC  57344      // 512 B
#define SMEM_TOTAL 57856

// ---------------------------------------------------------------------------
// Kernel 1: q_proj partials, K-split x4: grid (64 e-tiles, 4 k-splits).
// Each CTA: 16 e-rows x 32 b over K-range [ks*256, ks*256+256).
// Also: each of the 256 CTAs converts 1/256 of W2 to fp16 (g_w2h), and
// CTAs (bx<32, ks==0) zero ctx (d_out poisoned). Stream/event ordering
// (qproj -> score -> ... -> context) guarantees completion before use.
// ---------------------------------------------------------------------------
__global__ __launch_bounds__(256)
void qproj_kernel(const float* __restrict__ q,
                  const float* __restrict__ W1,
                  const float* __restrict__ W1b,
                  const float* __restrict__ W2,
                  float* __restrict__ qpart,
                  __half* __restrict__ w2h,
                  float* __restrict__ ctx) {
    __shared__ float4 qs4[32 * 32];   // 32 b x 32 chunks (swizzled)
    __shared__ float4 ws4[16 * 32];   // 16 e x 32 chunks

    const int tid = threadIdx.x;
    const int e0  = blockIdx.x * 16;
    const int ks  = blockIdx.y;        // 0..3
    const int b   = tid & 31;
    const int el  = tid >> 5;          // 0..7

    // W2 -> fp16 conversion slice (1024 float4 per CTA)
    {
        const int cid = ks * 64 + blockIdx.x;            // 0..255
        const float4* wsrc = (const float4*)W2 + (size_t)cid * 1024;
        uint2* wdst = (uint2*)w2h + (size_t)cid * 1024;
#pragma unroll
        for (int j = 0; j < 4; ++j) {
            const int idx = tid + j * 256;
            float4 v = wsrc[idx];
            wdst[idx] = make_uint2(packh2(v.x, v.y), packh2(v.z, v.w));
        }
    }

    if (ks == 0 && blockIdx.x < 32) {
#pragma unroll
        for (int i = 0; i < 4; ++i)
            ctx[(size_t)blockIdx.x * DIM + tid + i * 256] = 0.f;
    }

    float acc0 = 0.f, acc1 = 0.f;

#pragma unroll
    for (int kt = 0; kt < 2; ++kt) {
        const int k0 = ks * 256 + kt * 128;
#pragma unroll
        for (int j = 0; j < 4; ++j) {
            int i   = tid + j * 256;
            int row = i >> 5;
            int c4  = i & 31;
            float4 v = *(const float4*)(q + (size_t)row * DIM + k0 + c4 * 4);
            qs4[row * 32 + (c4 ^ row)] = v;
        }
#pragma unroll
        for (int j = 0; j < 2; ++j) {
            int i   = tid + j * 256;
            int row = i >> 5;
            int c4  = i & 31;
            ws4[row * 32 + c4] =
                *(const float4*)(W1 + (size_t)(e0 + row) * DIM + k0 + c4 * 4);
        }
        __syncthreads();
#pragma unroll
        for (int c = 0; c < 32; ++c) {
            float4 qv = qs4[b * 32 + (c ^ b)];
            float4 w0 = ws4[el * 32 + c];
            float4 w1 = ws4[(el + 8) * 32 + c];
            acc0 += qv.x * w0.x + qv.y * w0.y + qv.z * w0.z + qv.w * w0.w;
            acc1 += qv.x * w1.x + qv.y * w1.y + qv.z * w1.z + qv.w * w1.w;
        }
        __syncthreads();
    }
    float* qo = qpart + (size_t)ks * QP;
    const float b0 = (ks == 0) ? W1b[e0 + el]     : 0.f;
    const float b1 = (ks == 0) ? W1b[e0 + el + 8] : 0.f;
    qo[b * DIM + e0 + el]     = acc0 + b0;
    qo[b * DIM + e0 + el + 8] = acc1 + b1;
}

// ---------------------------------------------------------------------------
// Kernel 2 (dominant): fp16 mma.sync fused score GEMM, nt-split over
// blockIdx.y; each half writes its own partial buffer (no atomics).
// B (W2) is pre-converted fp16 — loaded straight to smem, no cvt.
//   score_part[y][m] = sum_{n in half} Vw[n]*tanh(D[m,n] + qproj[b,n] + W2b[n])
// qproj reconstructed from the 4 K-split partials at qsm load time.
// bx0 = row-tile offset (batch-split for stream overlap).
// (V_b dropped: softmax is shift-invariant and score is not an output.)
// ---------------------------------------------------------------------------
__global__ __launch_bounds__(256, 1)
void score_f16_kernel(const float* __restrict__ key,
                      const __half* __restrict__ w2h,
                      const float* __restrict__ W2b,
                      const float* __restrict__ qpart,
                      const float* __restrict__ Vw,
                      float* __restrict__ score_g,
                      int bx0) {
    extern __shared__ char smem[];
    const uint32_t sb = smem_u32(smem);
    float* qsm = (float*)(smem + OFF_QSM);
    float* vsm = (float*)(smem + OFF_VSM);
    float* score_sm = (float*)(smem + OFF_SC);

    const int tid  = threadIdx.x;
    const int lane = tid & 31;
    const int wid  = tid >> 5;
    const int warp_m = wid >> 2;        // 0..1
    const int warp_n = wid & 3;         // 0..3
    const int row0 = (blockIdx.x + bx0) * 128;
    const int b    = row0 >> 11;
    const int nt0  = blockIdx.y * 2;    // this CTA's nt range: nt0, nt0+1

    for (int i = tid; i < DIM; i += 256) {
        const int o = b * DIM + i;
        qsm[i] = qpart[o] + qpart[QP + o] + qpart[2 * QP + o] + qpart[3 * QP + o]
               + W2b[i];
        vsm[i] = Vw[i];
    }
    if (tid < 128) score_sm[tid] = 0.f;
    __syncthreads();

    // ldmatrix lane constants (chunk = 8 fp16 = one k8 half of a k16 step)
    const int r8      = lane & 7;
    const int mlocal  = (((lane >> 3) & 1) << 3) + r8;  // A x4 row-in-frag
    const int a_chalf = lane >> 4;                      // A: k8-half select
    const int b_chalf = (lane >> 3) & 1;                // B: k8-half select
    const int mrow_t  = warp_m * 64 + mlocal;           // + mf*16
    const int nrow_t  = warp_n * 64 + r8;               // + nf*8

    // global-load lane mapping: thread -> (row, 16B-fp16 chunk)
    const int gm = tid >> 2;            // 0..63 (+64 per iter)
    const int gc = tid & 3;             // chunk 0..3

    const float* keyA = key + (size_t)row0 * DIM;

    float sp[8];
#pragma unroll
    for (int j = 0; j < 8; ++j) sp[j] = 0.f;

    const uint32_t offA[2] = {OFF_A0, OFF_A1};
    const uint32_t offB[2] = {OFF_B0, OFF_B1};

    for (int p = 0; p < 2; ++p) {
        const int nt = nt0 + p;
        const __half* w2p = w2h + (size_t)(nt * 256) * DIM;

        float acc[4][8][4];
#pragma unroll
        for (int mf = 0; mf < 4; ++mf)
#pragma unroll
            for (int nf = 0; nf < 8; ++nf)
#pragma unroll
                for (int q = 0; q < 4; ++q) acc[mf][nf][q] = 0.f;

        float4 ra[2][2];
        uint4  rbh[4];
        // prologue: k-chunk 0 -> buf 0
#pragma unroll
        for (int i = 0; i < 2; ++i) {
            const float* pp = keyA + (size_t)(gm + i * 64) * DIM + gc * 8;
            ra[i][0] = *(const float4*)pp;
            ra[i][1] = *(const float4*)(pp + 4);
        }
#pragma unroll
        for (int i = 0; i < 4; ++i)
            rbh[i] = *(const uint4*)(w2p + (size_t)(gm + i * 64) * DIM + gc * 8);
#pragma unroll
        for (int i = 0; i < 2; ++i) {
            uint4 v = { packh2(ra[i][0].x, ra[i][0].y), packh2(ra[i][0].z, ra[i][0].w),
                        packh2(ra[i][1].x, ra[i][1].y), packh2(ra[i][1].z, ra[i][1].w) };
            *(uint4*)(smem + OFF_A0 + swz(gm + i * 64, gc)) = v;
        }
#pragma unroll
        for (int i = 0; i < 4; ++i)
            *(uint4*)(smem + OFF_B0 + swz(gm + i * 64, gc)) = rbh[i];
        __syncthreads();

        for (int kc = 0; kc < 32; ++kc) {          // 32 chunks of K=32 fp16
            const int buf = kc & 1;
            const bool more = kc < 31;
            if (more) {
                const int k0 = (kc + 1) * 32;
#pragma unroll
                for (int i = 0; i < 2; ++i) {
                    const float* pp = keyA + (size_t)(gm + i * 64) * DIM + k0 + gc * 8;
                    ra[i][0] = *(const float4*)pp;
                    ra[i][1] = *(const float4*)(pp + 4);
                }
#pragma unroll
                for (int i = 0; i < 4; ++i)
                    rbh[i] = *(const uint4*)(w2p + (size_t)(gm + i * 64) * DIM + k0 + gc * 8);
            }

            const uint32_t ab = sb + offA[buf];
            const uint32_t bb = sb + offB[buf];
#pragma unroll
            for (int s = 0; s < 2; ++s) {          // two k16 MMA steps
                uint32_t afr[4][4];
                uint32_t bfr[8][2];
#pragma unroll
                for (int mf = 0; mf < 4; ++mf)
                    ldsm4(afr[mf], ab + swz(mrow_t + mf * 16, 2 * s + a_chalf));
#pragma unroll
                for (int nf = 0; nf < 8; ++nf)
                    ldsm2(bfr[nf], bb + swz(nrow_t + nf * 8, 2 * s + b_chalf));
#pragma unroll
                for (int mf = 0; mf < 4; ++mf)
#pragma unroll
                    for (int nf = 0; nf < 8; ++nf)
                        mma_f16(acc[mf][nf], afr[mf], bfr[nf]);
            }

            if (more) {
                const int nbuf = buf ^ 1;
#pragma unroll
                for (int i = 0; i < 2; ++i) {
                    uint4 v = { packh2(ra[i][0].x, ra[i][0].y), packh2(ra[i][0].z, ra[i][0].w),
                                packh2(ra[i][1].x, ra[i][1].y), packh2(ra[i][1].z, ra[i][1].w) };
                    *(uint4*)(smem + offA[nbuf] + swz(gm + i * 64, gc)) = v;
                }
#pragma unroll
                for (int i = 0; i < 4; ++i)
                    *(uint4*)(smem + offB[nbuf] + swz(gm + i * 64, gc)) = rbh[i];
                __syncthreads();
            }
        }

        // fused epilogue: tanh + V-dot into per-thread row partials
        const int ncol0 = nt * 256 + warp_n * 64 + (lane & 3) * 2;
#pragma unroll
        for (int mf = 0; mf < 4; ++mf) {
#pragma unroll
            for (int nf = 0; nf < 8; ++nf) {
                const int n0 = ncol0 + nf * 8;
                const float q0 = qsm[n0],     v0 = vsm[n0];
                const float q1 = qsm[n0 + 1], v1 = vsm[n0 + 1];
                float* c4 = acc[mf][nf];
                sp[mf * 2 + 0] += tanh_fast(c4[0] + q0) * v0 + tanh_fast(c4[1] + q1) * v1;
                sp[mf * 2 + 1] += tanh_fast(c4[2] + q0) * v0 + tanh_fast(c4[3] + q1) * v1;
            }
        }
        // next pass's prologue STS targets buf0; gated by its own __syncthreads()
    }

    // reduce quad (lanes sharing the same row) and accumulate to smem
#pragma unroll
    for (int j = 0; j < 8; ++j) {
        float v = sp[j];
        v += __shfl_xor_sync(0xffffffffu, v, 1);
        v += __shfl_xor_sync(0xffffffffu, v, 2);
        if ((lane & 3) == 0) {
            const int row = warp_m * 64 + (j >> 1) * 16 + (j & 1) * 8 + (lane >> 2);
            atomicAdd(&score_sm[row], v);
        }
    }
    __syncthreads();
    if (tid < 128)
        score_g[blockIdx.y * MROWS + row0 + tid] = score_sm[tid];   // plain store
}

// ---------------------------------------------------------------------------
// Kernel 3: softmax over S per batch row (sums the two partial buffers),
// writes attn. b0 = batch offset for the batch-split launches.
// ---------------------------------------------------------------------------
__global__ void softmax_kernel(const float* __restrict__ score,
                               float* __restrict__ attn, int b0) {
    const int b   = blockIdx.x + b0;
    const int tid = threadIdx.x;   // 256
    __shared__ float red[256];
    const float* sr0 = score + (size_t)b * SEQ;
    const float* sr1 = score + MROWS + (size_t)b * SEQ;

    float v[8];
    float mx = -INFINITY;
#pragma unroll
    for (int i = 0; i < 8; ++i) {
        const int idx = tid + i * 256;
        v[i] = sr0[idx] + sr1[idx];
        mx = fmaxf(mx, v[i]);
    }
    red[tid] = mx;
    __syncthreads();
    for (int s = 128; s; s >>= 1) {
        if (tid < s) red[tid] = fmaxf(red[tid], red[tid + s]);
        __syncthreads();
    }
    const float m = red[0];
    __syncthreads();

    float sum = 0.f;
#pragma unroll
    for (int i = 0; i < 8; ++i) {
        v[i] = expf(v[i] - m);
        sum += v[i];
    }
    red[tid] = sum;
    __syncthreads();
    for (int s = 128; s; s >>= 1) {
        if (tid < s) red[tid] += red[tid + s];
        __syncthreads();
    }
    const float inv = 1.f / red[0];
#pragma unroll
    for (int i = 0; i < 8; ++i)
        attn[(size_t)b * SEQ + tid + i * 256] = v[i] * inv;
}

// ---------------------------------------------------------------------------
// Kernel 4: context[b,d] += sum_{s in chunk} attn[b,s] * value[b,s,d]
// grid (nb, 32 s-chunks) x 256 thr; each thread owns one float4 of d.
// b0 = batch offset for the batch-split launches.
// ---------------------------------------------------------------------------
__global__ __launch_bounds__(256)
void context_kernel(const float* __restrict__ attn,
                    const float* __restrict__ value,
                    float* __restrict__ ctx, int b0) {
    const int b   = blockIdx.x + b0;
    const int s0  = blockIdx.y * 64;
    const int tid = threadIdx.x;
    __shared__ float a_sh[64];

    if (tid < 64) a_sh[tid] = attn[(size_t)b * SEQ + s0 + tid];
    __syncthreads();

    const float4* vp = (const float4*)(value + ((size_t)b * SEQ + s0) * DIM) + tid;
    float ax = 0.f, ay = 0.f, az = 0.f, aw = 0.f;
#pragma unroll 8
    for (int s = 0; s < 64; ++s) {
        const float a = a_sh[s];
        const float4 w = vp[(size_t)s * 256];
        ax = fmaf(a, w.x, ax);
        ay = fmaf(a, w.y, ay);
        az = fmaf(a, w.z, az);
        aw = fmaf(a, w.w, aw);
    }
    float* cp = ctx + (size_t)b * DIM + tid * 4;
    atomicAdd(cp + 0, ax);
    atomicAdd(cp + 1, ay);
    atomicAdd(cp + 2, az);
    atomicAdd(cp + 3, aw);
}

// ---------------------------------------------------------------------------
extern "C" void kernel_launch(void* const* d_in, const int* in_sizes, int n_in,
                              void* d_out, int out_size) {
    const float* query = (const float*)d_in[0];
    const float* key   = (const float*)d_in[1];
    const float* value = (const float*)d_in[2];
    const float* W1w   = (const float*)d_in[3];
    const float* W1b   = (const float*)d_in[4];
    const float* W2w   = (const float*)d_in[5];
    const float* W2b   = (const float*)d_in[6];
    const float* Vw    = (const float*)d_in[7];
    // d_in[8] = V_b: dropped — softmax is shift-invariant, score not an output

    float* out  = (float*)d_out;
    float* ctx  = out;                        // [B, DIM]
    float* attn = out + (size_t)BATCH * DIM;  // [B, S]

    float*  qpart;  cudaGetSymbolAddress((void**)&qpart, g_qpart);
    float*  score;  cudaGetSymbolAddress((void**)&score, g_score);
    __half* w2h;    cudaGetSymbolAddress((void**)&w2h, g_w2h);

    cudaFuncSetAttribute(score_f16_kernel,
                         cudaFuncAttributeMaxDynamicSharedMemorySize, SMEM_TOTAL);

    // Fork/join stream for overlap. Created per call and intentionally not
    // destroyed (destroying a capturing stream invalidates capture);
    // kernel_launch runs only for correctness + capture, so the leak is 2
    // host objects. No device memory is allocated.
    int prLo = 0, prHi = 0;
    cudaDeviceGetStreamPriorityRange(&prLo, &prHi);
    cudaStream_t s2;
    cudaStreamCreateWithPriority(&s2, cudaStreamNonBlocking, prLo);  // low prio
    cudaEvent_t eQ, eJ;
    cudaEventCreateWithFlags(&eQ, cudaEventDisableTiming);
    cudaEventCreateWithFlags(&eJ, cudaEventDisableTiming);

    // 1) q_proj K-split x4 partials; also converts W2->fp16 and zeroes ctx
    qproj_kernel<<<dim3(64, 4), 256>>>(query, W1w, W1b, W2w, qpart, w2h, ctx);
    cudaEventRecord(eQ, 0);

    // 2a) score G1: batches [0, B_G1) on the legacy stream (captured first
    //     so its CTAs lead in dispatch order)
    score_f16_kernel<<<dim3(B_G1 * 16, 2), 256, SMEM_TOTAL>>>(
        key, w2h, W2b, qpart, Vw, score, 0);

    // 2b) score G2: batches [B_G1, 32) on the forked low-priority stream,
    //     dependent only on qproj
    cudaStreamWaitEvent(s2, eQ, 0);
    score_f16_kernel<<<dim3((BATCH - B_G1) * 16, 2), 256, SMEM_TOTAL, s2>>>(
        key, w2h, W2b, qpart, Vw, score, B_G1 * 16);
    cudaEventRecord(eJ, s2);

    // 3a) softmax + context for G1 on legacy — runs after score G1, overlapping
    //     score G2 (complementary pipes: HBM-bound vs tensor-bound)
    softmax_kernel<<<B_G1, 256>>>(score, attn, 0);
    context_kernel<<<dim3(B_G1, 32), 256>>>(attn, value, ctx, 0);

    // 3b) join G2, then its softmax + context
    cudaStreamWaitEvent(0, eJ, 0);
    softmax_kernel<<<BATCH - B_G1, 256>>>(score, attn, B_G1);
    context_kernel<<<dim3(BATCH - B_G1, 32), 256>>>(attn, value, ctx, B_G1);
}